// round 1
// baseline (speedup 1.0000x reference)
#include <cuda_runtime.h>

#define N_PATHS 8
#define N_FEAT 128
#define CART 3
#define N_SPECIES 10
#define ROW_STRIDE 4096          // x row length
#define OUT_PER_ATOM (N_FEAT * CART)   // 384
#define BLOCK_SLICE (N_FEAT * CART)    // 384 floats per p-chunk in x

__global__ __launch_bounds__(OUT_PER_ATOM, 4)
void wps_kernel(const float* __restrict__ x,
                const float* __restrict__ y,
                const float* __restrict__ w,
                float* __restrict__ out,
                int n_atoms)
{
    const int n = blockIdx.x;
    if (n >= n_atoms) return;

    const int tid = threadIdx.x;   // 0..383 -> output element f*3+c

    __shared__ int s_species;
    __shared__ float s_w[N_PATHS * N_FEAT];   // 1024 floats = 4KB

    // --- find species from one-hot row ---
    if (tid < N_SPECIES) {
        if (y[(size_t)n * N_SPECIES + tid] > 0.5f) s_species = tid;
    }
    __syncthreads();
    const int s = s_species;

    // --- stage weight[s] into smem ---
    const float* wsrc = w + (size_t)s * (N_PATHS * N_FEAT);
    #pragma unroll
    for (int i = tid; i < N_PATHS * N_FEAT; i += OUT_PER_ATOM) {
        s_w[i] = wsrc[i];
    }
    __syncthreads();

    const int f = tid / CART;     // feature index for this output element
    const float* xrow = x + (size_t)n * ROW_STRIDE;

    float acc = 0.0f;
    #pragma unroll
    for (int p = 0; p < N_PATHS; ++p) {
        acc = fmaf(s_w[p * N_FEAT + f], xrow[p * BLOCK_SLICE + tid], acc);
    }

    out[(size_t)n * OUT_PER_ATOM + tid] = acc;
}

extern "C" void kernel_launch(void* const* d_in, const int* in_sizes, int n_in,
                              void* d_out, int out_size)
{
    const float* x = (const float*)d_in[0];   // [N, 4096]
    const float* y = (const float*)d_in[1];   // [N, 10] one-hot
    const float* w = (const float*)d_in[2];   // [10, 8, 128]
    float* out = (float*)d_out;               // [N, 384]

    const int n_atoms = in_sizes[0] / ROW_STRIDE;

    wps_kernel<<<n_atoms, OUT_PER_ATOM>>>(x, y, w, out, n_atoms);
}

// round 2
// speedup vs baseline: 1.2265x; 1.2265x over previous
#include <cuda_runtime.h>

#define N_PATHS   8
#define N_FEAT    128
#define CART      3
#define N_SPECIES 10
#define ROW_F4    1024          // 4096 floats per x row = 1024 float4
#define OUT_F4    96            // 384 floats per out row = 96 float4
#define TPB       384
#define SLOTS     4             // atoms processed per CTA per iteration
#define LPA       96            // lanes (threads) per atom, one float4 each
#define W_FLOATS  (N_SPECIES * N_PATHS * N_FEAT)   // 10240 floats = 40 KB

__global__ __launch_bounds__(TPB, 4)
void wps_kernel(const float4* __restrict__ x,
                const float*  __restrict__ y,
                const float4* __restrict__ w4,
                float4* __restrict__ out,
                int n_atoms)
{
    __shared__ float s_w[W_FLOATS];   // all species' weights: 40 KB

    // ---- stage ALL weights once per CTA (vectorized) ----
    float4* s_w4 = reinterpret_cast<float4*>(s_w);
    #pragma unroll
    for (int i = threadIdx.x; i < W_FLOATS / 4; i += TPB)
        s_w4[i] = w4[i];
    __syncthreads();   // the ONLY barrier in the kernel

    const int slot = threadIdx.x / LPA;    // 0..3 : which atom in the group
    const int lane = threadIdx.x % LPA;    // 0..95: which float4 of the output

    // the 4 output elements e = 4*lane .. 4*lane+3 span exactly 2 features
    const int e0 = lane * 4;
    const int f0 = e0 / CART;              // first feature
    const int r  = e0 - f0 * CART;         // e0 % 3, fixed per thread

    const int stride_atoms = gridDim.x * SLOTS;

    for (int a = blockIdx.x * SLOTS + slot; a < n_atoms; a += stride_atoms) {
        // ---- species from one-hot row (uniform within the 96-lane group,
        //      broadcast loads; no barrier needed) ----
        const float* yrow = y + (size_t)a * N_SPECIES;
        int s = 0;
        #pragma unroll
        for (int k = 1; k < N_SPECIES; ++k)
            s = (yrow[k] > 0.5f) ? k : s;

        const float*  wsp  = s_w + s * (N_PATHS * N_FEAT);
        const float4* xrow = x + (size_t)a * ROW_F4;

        float4 acc = {0.f, 0.f, 0.f, 0.f};
        #pragma unroll
        for (int p = 0; p < N_PATHS; ++p) {
            float4 xv = __ldcs(&xrow[p * LPA + lane]);   // streaming read-once
            const float* wp = wsp + p * N_FEAT;
            float wa = wp[f0];
            float wb = wp[f0 + 1];
            // component-to-feature map depends only on r:
            //   r=0: (wa,wa,wa,wb)   r=1: (wa,wa,wb,wb)   r=2: (wa,wb,wb,wb)
            float wy = (r == 2) ? wb : wa;
            float wz = (r == 0) ? wa : wb;
            acc.x = fmaf(xv.x, wa, acc.x);
            acc.y = fmaf(xv.y, wy, acc.y);
            acc.z = fmaf(xv.z, wz, acc.z);
            acc.w = fmaf(xv.w, wb, acc.w);
        }

        __stcs(&out[(size_t)a * OUT_F4 + lane], acc);
    }
}

extern "C" void kernel_launch(void* const* d_in, const int* in_sizes, int n_in,
                              void* d_out, int out_size)
{
    const float4* x  = (const float4*)d_in[0];   // [N, 4096] fp32
    const float*  y  = (const float*) d_in[1];   // [N, 10] one-hot
    const float4* w4 = (const float4*)d_in[2];   // [10, 8, 128] fp32
    float4* out = (float4*)d_out;                // [N, 384] fp32

    const int n_atoms = in_sizes[0] / 4096;

    int grid = 148 * 4;                          // 4 CTAs/SM, grid-strided
    int max_grid = (n_atoms + SLOTS - 1) / SLOTS;
    if (grid > max_grid) grid = max_grid;

    wps_kernel<<<grid, TPB>>>(x, y, w4, out, n_atoms);
}

// round 3
// speedup vs baseline: 1.2405x; 1.0114x over previous
#include <cuda_runtime.h>

#define N_PATHS   8
#define N_FEAT    128
#define CART      3
#define N_SPECIES 10
#define ROW_F4    1024          // 4096 floats per x row = 1024 float4
#define OUT_F4    96            // 384 floats per out row = 96 float4
#define TPB       384
#define SLOTS     4             // atoms per CTA per iteration
#define LPA       96            // lanes per atom, one float4 each

__global__ __launch_bounds__(TPB, 5)
void wps_kernel(const float4* __restrict__ x,
                const float*  __restrict__ y,
                const float*  __restrict__ w,
                float4* __restrict__ out,
                int n_atoms)
{
    const int slot = threadIdx.x / LPA;    // 0..3 : which atom in the group
    const int lane = threadIdx.x % LPA;    // 0..95: which float4 of the output

    // the 4 output elements e = 4*lane .. 4*lane+3 span exactly 2 features
    const int e0 = lane * 4;
    const int f0 = e0 / CART;              // first feature
    const int r  = e0 - f0 * CART;         // e0 % 3, fixed per thread

    const int stride_atoms = gridDim.x * SLOTS;

    for (int a = blockIdx.x * SLOTS + slot; a < n_atoms; a += stride_atoms) {
        // ---- species from one-hot row (broadcast loads, L1/L2 resident) ----
        const float* yrow = y + (size_t)a * N_SPECIES;
        int s = 0;
        #pragma unroll
        for (int k = 1; k < N_SPECIES; ++k)
            s = (__ldg(&yrow[k]) > 0.5f) ? k : s;

        // weight row for this species: L1-resident (40 KB table, x is evict-first)
        const float*  wsp  = w + s * (N_PATHS * N_FEAT) + f0;
        const float4* xrow = x + (size_t)a * ROW_F4;

        float4 acc = {0.f, 0.f, 0.f, 0.f};
        #pragma unroll
        for (int p = 0; p < N_PATHS; ++p) {
            float4 xv = __ldcs(&xrow[p * LPA + lane]);   // streaming read-once
            float wa = __ldg(&wsp[p * N_FEAT]);
            float wb = __ldg(&wsp[p * N_FEAT + 1]);
            // component-to-feature map, fixed per thread by r:
            //   r=0: (wa,wa,wa,wb)  r=1: (wa,wa,wb,wb)  r=2: (wa,wb,wb,wb)
            float wy = (r == 2) ? wb : wa;
            float wz = (r == 0) ? wa : wb;
            acc.x = fmaf(xv.x, wa, acc.x);
            acc.y = fmaf(xv.y, wy, acc.y);
            acc.z = fmaf(xv.z, wz, acc.z);
            acc.w = fmaf(xv.w, wb, acc.w);
        }

        __stcs(&out[(size_t)a * OUT_F4 + lane], acc);
    }
}

extern "C" void kernel_launch(void* const* d_in, const int* in_sizes, int n_in,
                              void* d_out, int out_size)
{
    const float4* x = (const float4*)d_in[0];   // [N, 4096] fp32
    const float*  y = (const float*) d_in[1];   // [N, 10] one-hot
    const float*  w = (const float*) d_in[2];   // [10, 8, 128] fp32
    float4* out = (float4*)d_out;               // [N, 384] fp32

    const int n_atoms = in_sizes[0] / 4096;

    int grid = 148 * 5;                          // 5 CTAs/SM, persistent grid-stride
    int max_grid = (n_atoms + SLOTS - 1) / SLOTS;
    if (grid > max_grid) grid = max_grid;

    wps_kernel<<<grid, TPB>>>(x, y, w, out, n_atoms);
}